// round 15
// baseline (speedup 1.0000x reference)
#include <cuda_runtime.h>

#define FULLMASK 0xffffffffu

constexpr int   B_     = 256;
constexpr int   T_     = 256;
constexpr int   C_     = 1024;
constexpr int   L_     = 32;
constexpr int   BLANK_ = C_ - 1;
constexpr int   GP_    = 11;      // float4 groups per row
constexpr int   RF_    = 44;      // floats per row
constexpr float PRE    = 512.0f;
constexpr int   PRE_E  = 9;
constexpr float EPS    = 1e-7f;
constexpr float EPS_S  = EPS * PRE;

// transposed compact scratch: row (b,t) = 11 float4 groups of
// [lab(3L), lab(3L+1), lab(3L+2), blank]; group10.z = 0 pad
__device__ float g_scr[(size_t)B_ * T_ * RF_];
__device__ int   g_cnt[2][B_];        // per-(half,batch) chunk count
__device__ int   g_done[B_];          // per-batch published-half count
__device__ float g_ex[2][B_][66];     // boundary states
__device__ int   g_exE[2][B_];        // renorm exponents

__device__ __forceinline__ float ldg_cg(const float* p) {
    float v;
    asm volatile("ld.global.cg.f32 %0, [%1];" : "=f"(v) : "l"(p));
    return v;
}
__device__ __forceinline__ int renorm6(float& r0, float& r1, float& r2,
                                       float& r3, float& r4, float& r5) {
    float m = fmaxf(fmaxf(fmaxf(r0, r1), fmaxf(r2, r3)), fmaxf(r4, r5));
    int im = __float_as_int(m);
    asm volatile("redux.sync.max.s32 %0, %1, 0x7ff;" : "=r"(im) : "r"(im));
    const int e = (im >> 23) - 127;
    const float sc = __int_as_float((127 - e) << 23);  // exact 2^-e
    r0 *= sc; r1 *= sc; r2 *= sc; r3 *= sc; r4 *= sc; r5 *= sc;
    return e;
}

__global__ __launch_bounds__(256)
void ctc_fused_kernel(const int* __restrict__ y_true,
                      const float* __restrict__ y_pred,
                      float* __restrict__ out)
{
    __shared__ int labsx[33];      // [blank, lab0..lab31] — ONLY smem
    __shared__ int s_role;

    const int bid   = blockIdx.x;
    const int b     = bid >> 3;
    const int cidx  = bid & 7;
    const int chunk = cidx << 5;
    const int half  = cidx >> 2;
    const int tid   = threadIdx.x;
    const int lane  = tid & 31;
    const int wid   = tid >> 5;

    if (tid < 33)
        labsx[tid] = tid ? __ldg(y_true + b * L_ + tid - 1) : BLANK_;
    __syncthreads();

    // ---- gather: 32 rows x 33 loads (blank once), fan-out stores ----------
    {
        const float* base = y_pred + ((size_t)b * T_ + chunk) * C_;
        float v[5];
        int   rr[5], ww[5];
#pragma unroll
        for (int i = 0; i < 5; ++i) {
            const int f = tid + i * 256;
            if (f < 1056) {
                const int row = f / 33;
                const int w   = f - 33 * row;
                rr[i] = row; ww[i] = w;
                const int cls = (w < 32) ? labsx[1 + w] : labsx[0];
                v[i] = ldg_cg(base + (size_t)row * C_ + cls);
            }
        }
#pragma unroll
        for (int i = 0; i < 5; ++i) {
            const int f = tid + i * 256;
            if (f < 1056) {
                float* orow = g_scr + ((size_t)b * T_ + chunk + rr[i]) * RF_;
                const float val = fmaf(v[i], PRE, EPS_S);
                if (ww[i] < 32) {
                    const int g = ww[i] / 3;
                    orow[g * 4 + (ww[i] - 3 * g)] = val;
                } else {
#pragma unroll
                    for (int k = 0; k < 11; ++k) orow[4 * k + 3] = val;
                    orow[42] = 0.0f;   // pad state
                }
            }
        }
    }
    __threadfence();
    __syncthreads();

    // ---- last arriver of this half scans it (1 warp, no smem, no copy) ----
    if (tid == 0)
        s_role = (atomicAdd(&g_cnt[half][b], 1) == 3);
    __syncthreads();
    if (!s_role || wid != 0) return;

    __threadfence();   // order scratch reads after the count observation

    const unsigned M = 0x7FFu;
    const int* labs = labsx + 1;
    const int Lx = lane;
    const float4* rowp = ((const float4*)(g_scr + (size_t)b * T_ * RF_)) + Lx;

    const unsigned nzm = __ballot_sync(FULLMASK, labsx[1 + lane] != 0);
    const int len = __popc(nzm);

    float R0 = 0, R1 = 0, R2 = 0, R3 = 0, R4 = 0, R5 = 0;
    int   E  = 0;

    if (lane < 11) {
        float r0 = 0, r1 = 0, r2 = 0, r3 = 0, r4 = 0, r5 = 0;
        float4 q[8];

        if (half == 0) {
            // ---- forward: alpha_0 .. alpha_127 over rows 0..127 ----
            const float a1 = (Lx == 0 || labs[3*Lx] != labs[3*Lx - 1]) ? 1.0f : 0.0f;
            const float a3 = (labs[3*Lx + 1] != labs[3*Lx]) ? 1.0f : 0.0f;
            const float a5 = (Lx < 10 && labs[3*Lx + 2] != labs[3*Lx + 1]) ? 1.0f : 0.0f;

            {
                const float4 q0 = rowp[0];
                if (Lx == 0) { r0 = q0.w; r1 = q0.x; }
            }
#pragma unroll
            for (int j = 0; j < 8; ++j) q[j] = rowp[GP_ * (1 + j)];

#define FSTEP(tt, idx) {                                              \
                const float4 qq = q[idx];                             \
                q[idx] = rowp[GP_ * ((tt) + 8)];                      \
                float u5 = __shfl_up_sync(M, r5, 1);                  \
                u5 = Lx ? u5 : 0.0f;                                  \
                const float n0 = qq.w * (r0 + u5);                    \
                const float n1 = qq.x * fmaf(a1, u5, r1 + r0);        \
                const float n2 = qq.w * (r2 + r1);                    \
                const float n3 = qq.y * fmaf(a3, r1, r3 + r2);        \
                const float n4 = qq.w * (r4 + r3);                    \
                const float n5 = qq.z * fmaf(a5, r3, r5 + r4);        \
                r0 = n0; r1 = n1; r2 = n2; r3 = n3; r4 = n4; r5 = n5; }

            // t = 1..7 consume q[0..6]
#pragma unroll
            for (int j = 1; j < 8; ++j) FSTEP(j, j - 1);
            E += renorm6(r0, r1, r2, r3, r4, r5);
            // t = 8..127, idx = (t-1) & 7 = (j+7) & 7 (tb multiple of 8)
            for (int tb = 8; tb < 128; tb += 8) {
#pragma unroll
                for (int j = 0; j < 8; ++j) FSTEP(tb + j, (j + 7) & 7);
                E += renorm6(r0, r1, r2, r3, r4, r5);
            }
#undef FSTEP
            R0 = r0; R1 = r1; R2 = r2; R3 = r3; R4 = r4; R5 = r5;
        } else {
            // ---- backward: c_t = p_t*beta_t, rows 255..128 ----
            int ilb = 2 * len;
            int ill = 2 * len - 1;
            if (ill < 0) ill += 65;

            const float b1 = (labs[3*Lx + 1] != labs[3*Lx]) ? 1.0f : 0.0f;
            const float b3 = (Lx < 10 && labs[3*Lx + 2] != labs[3*Lx + 1]) ? 1.0f : 0.0f;
            const float b5 = (Lx < 10 && labs[3*Lx + 3] != labs[3*Lx + 2]) ? 1.0f : 0.0f;

            {
                const float4 q0 = rowp[GP_ * 255];
                const int s = 6 * Lx;
                r0 = (s     == ilb || s     == ill) ? q0.w : 0.0f;
                r1 = (s + 1 == ilb || s + 1 == ill) ? q0.x : 0.0f;
                r2 = (s + 2 == ilb || s + 2 == ill) ? q0.w : 0.0f;
                r3 = (s + 3 == ilb || s + 3 == ill) ? q0.y : 0.0f;
                r4 = (s + 4 == ilb || s + 4 == ill) ? q0.w : 0.0f;
                r5 = (s + 5 == ilb || s + 5 == ill) ? q0.z : 0.0f;
            }
#pragma unroll
            for (int j = 0; j < 8; ++j) q[j] = rowp[GP_ * (254 - j)];

#define BSTEP(tt, idx) {                                              \
                const float4 qq = q[idx];                             \
                q[idx] = rowp[GP_ * ((tt) - 8)];                      \
                float d0 = __shfl_down_sync(M, r0, 1);                \
                float d1 = __shfl_down_sync(M, r1, 1);                \
                d0 = (Lx < 10) ? d0 : 0.0f;                           \
                d1 = (Lx < 10) ? d1 : 0.0f;                           \
                const float n0 = qq.w * (r0 + r1);                    \
                const float n1 = qq.x * fmaf(b1, r3, r1 + r2);        \
                const float n2 = qq.w * (r2 + r3);                    \
                const float n3 = qq.y * fmaf(b3, r5, r3 + r4);        \
                const float n4 = qq.w * (r4 + r5);                    \
                const float n5 = qq.z * fmaf(b5, d1, r5 + d0);        \
                r0 = n0; r1 = n1; r2 = n2; r3 = n3; r4 = n4; r5 = n5; }

            // t = 254..248 consume q[0..6]
#pragma unroll
            for (int j = 0; j < 7; ++j) BSTEP(254 - j, j);
            E += renorm6(r0, r1, r2, r3, r4, r5);
            // t = 247..128, idx = (254-t) & 7 = (j+7) & 7 for t = tb - j
            for (int tb = 247; tb >= 135; tb -= 8) {
#pragma unroll
                for (int j = 0; j < 8; ++j) BSTEP(tb - j, (j + 7) & 7);
                E += renorm6(r0, r1, r2, r3, r4, r5);
            }
#undef BSTEP

            // beta_127 combine (no p multiply) from c_128
            float d0 = __shfl_down_sync(M, r0, 1);
            float d1 = __shfl_down_sync(M, r1, 1);
            d0 = (Lx < 10) ? d0 : 0.0f;
            d1 = (Lx < 10) ? d1 : 0.0f;
            R0 = r0 + r1;
            R1 = fmaf(b1, r3, r1 + r2);
            R2 = r2 + r3;
            R3 = fmaf(b3, r5, r3 + r4);
            R4 = r4 + r5;
            R5 = fmaf(b5, d1, r5 + d0);
        }

        const int s = 6 * Lx;
        g_ex[half][b][s]     = R0;
        g_ex[half][b][s + 1] = R1;
        g_ex[half][b][s + 2] = R2;
        g_ex[half][b][s + 3] = R3;
        g_ex[half][b][s + 4] = R4;
        g_ex[half][b][s + 5] = R5;
    }

    int oldd = 0;
    if (lane == 0) {
        g_exE[half][b] = E;
        __threadfence();
        oldd = atomicAdd(&g_done[b], 1);
        g_cnt[half][b] = 0;            // reset for next replay
    }
    oldd = __shfl_sync(FULLMASK, oldd, 0);

    if (oldd == 1) {
        __threadfence();
        float part = ldg_cg(&g_ex[0][b][lane])      * ldg_cg(&g_ex[1][b][lane])
                   + ldg_cg(&g_ex[0][b][lane + 32]) * ldg_cg(&g_ex[1][b][lane + 32]);
        if (lane < 2)
            part += ldg_cg(&g_ex[0][b][lane + 64]) * ldg_cg(&g_ex[1][b][lane + 64]);
#pragma unroll
        for (int o = 16; o; o >>= 1)
            part += __shfl_xor_sync(FULLMASK, part, o);
        if (lane == 0) {
            int e0, e1;
            asm volatile("ld.global.cg.s32 %0, [%1];" : "=r"(e0) : "l"(&g_exE[0][b]));
            asm volatile("ld.global.cg.s32 %0, [%1];" : "=r"(e1) : "l"(&g_exE[1][b]));
            const float LN2 = 0.6931471805599453f;
            out[b] = -(logf(part) + (float)(e0 + e1 - PRE_E * T_) * LN2);
            g_done[b] = 0;             // reset for next replay
        }
    }
}

extern "C" void kernel_launch(void* const* d_in, const int* in_sizes, int n_in,
                              void* d_out, int out_size)
{
    (void)n_in; (void)out_size;
    const int*   y_true;
    const float* y_pred;
    if (in_sizes[0] == B_ * L_) {
        y_true = (const int*)d_in[0];
        y_pred = (const float*)d_in[1];
    } else {
        y_true = (const int*)d_in[1];
        y_pred = (const float*)d_in[0];
    }
    ctc_fused_kernel<<<B_ * 8, 256>>>(y_true, y_pred, (float*)d_out);
}

// round 16
// speedup vs baseline: 1.1465x; 1.1465x over previous
#include <cuda_runtime.h>

#define FULLMASK 0xffffffffu

constexpr int   B_     = 256;
constexpr int   T_     = 256;
constexpr int   C_     = 1024;
constexpr int   L_     = 32;
constexpr int   BLANK_ = C_ - 1;
constexpr int   GP_    = 11;      // float4 groups per row
constexpr int   RF_    = 44;      // floats per row
constexpr float PRE    = 512.0f;
constexpr int   PRE_E  = 9;
constexpr float EPS    = 1e-7f;
constexpr float EPS_S  = EPS * PRE;

// transposed compact scratch: row (b,t) = 11 float4 groups of
// [lab(3L), lab(3L+1), lab(3L+2), blank]; group10.z = 0 pad
__device__ float g_scr[(size_t)B_ * T_ * RF_];

__device__ __forceinline__ float ldg_cs(const float* p) {
    float v;
    asm volatile("ld.global.cs.f32 %0, [%1];" : "=f"(v) : "l"(p));
    return v;
}
__device__ __forceinline__ int renorm6(float& r0, float& r1, float& r2,
                                       float& r3, float& r4, float& r5) {
    float m = fmaxf(fmaxf(fmaxf(r0, r1), fmaxf(r2, r3)), fmaxf(r4, r5));
    int im = __float_as_int(m);
    asm volatile("redux.sync.max.s32 %0, %1, 0x7ff;" : "=r"(im) : "r"(im));
    const int e = (im >> 23) - 127;
    const float sc = __int_as_float((127 - e) << 23);  // exact 2^-e
    r0 *= sc; r1 *= sc; r2 *= sc; r3 *= sc; r4 *= sc; r5 *= sc;
    return e;
}

// ---------------------------------------------------------------------------
// Kernel 1: saturating gather with streaming (.cs evict-first) y_pred reads.
// 33 loads/row (blank once), fan-out stores to the transposed layout.
// ---------------------------------------------------------------------------
__global__ __launch_bounds__(256)
void ctc_gather_kernel(const int* __restrict__ y_true,
                       const float* __restrict__ y_pred)
{
    __shared__ int labsx[33];   // [blank, lab0..lab31]

    const int bid   = blockIdx.x;
    const int b     = bid >> 3;
    const int chunk = (bid & 7) << 5;
    const int tid   = threadIdx.x;

    if (tid < 33)
        labsx[tid] = tid ? __ldg(y_true + b * L_ + tid - 1) : BLANK_;
    __syncthreads();

    const float* base = y_pred + ((size_t)b * T_ + chunk) * C_;

    float v[5];
    int   rr[5], ww[5];
#pragma unroll
    for (int i = 0; i < 5; ++i) {
        const int f = tid + i * 256;
        if (f < 1056) {
            const int row = f / 33;
            const int w   = f - 33 * row;
            rr[i] = row; ww[i] = w;
            const int cls = (w < 32) ? labsx[1 + w] : labsx[0];
            v[i] = ldg_cs(base + (size_t)row * C_ + cls);
        }
    }
#pragma unroll
    for (int i = 0; i < 5; ++i) {
        const int f = tid + i * 256;
        if (f < 1056) {
            float* orow = g_scr + ((size_t)b * T_ + chunk + rr[i]) * RF_;
            const float val = fmaf(v[i], PRE, EPS_S);
            if (ww[i] < 32) {
                const int g = ww[i] / 3;
                orow[g * 4 + (ww[i] - 3 * g)] = val;
            } else {
#pragma unroll
                for (int k = 0; k < 11; ++k) orow[4 * k + 3] = val;
                orow[42] = 0.0f;   // pad state
            }
        }
    }
}

// ---------------------------------------------------------------------------
// Kernel 2: per-batch scan straight from L2-resident scratch. 64 threads:
// warp 0 forward (t=0..127), warp 1 backward (t=255..128), combine in smem.
// ---------------------------------------------------------------------------
__global__ __launch_bounds__(64)
void ctc_scan_kernel(const int* __restrict__ y_true,
                     float* __restrict__ out)
{
    __shared__ int   labs[L_];
    __shared__ float exA[66], exB[66];
    __shared__ int   exE[2];

    const int b    = blockIdx.x;
    const int tid  = threadIdx.x;
    const int lane = tid & 31;
    const int wid  = tid >> 5;
    const unsigned M = 0x7FFu;

    if (tid < L_) labs[tid] = __ldg(y_true + b * L_ + tid);
    __syncthreads();

    const unsigned nzm = __ballot_sync(FULLMASK, labs[lane] != 0);
    const int len = __popc(nzm);

    const int Lx = lane;
    const float4* rowp = ((const float4*)(g_scr + (size_t)b * T_ * RF_)) + Lx;

    if (wid == 0 && lane < 11) {
        // ---------------- forward: alpha_0 .. alpha_127 ----------------
        const float a1 = (Lx == 0 || labs[3*Lx] != labs[3*Lx - 1]) ? 1.0f : 0.0f;
        const float a3 = (labs[3*Lx + 1] != labs[3*Lx]) ? 1.0f : 0.0f;
        const float a5 = (Lx < 10 && labs[3*Lx + 2] != labs[3*Lx + 1]) ? 1.0f : 0.0f;

        float r0 = 0, r1 = 0, r2 = 0, r3 = 0, r4 = 0, r5 = 0;
        {
            const float4 q0 = rowp[0];
            if (Lx == 0) { r0 = q0.w; r1 = q0.x; }
        }
        float4 q[8];
#pragma unroll
        for (int j = 0; j < 8; ++j) q[j] = rowp[GP_ * (1 + j)];
        int E = 0;

#define FSTEP(tt, idx) {                                              \
            const float4 qq = q[idx];                                 \
            q[idx] = rowp[GP_ * ((tt) + 8)];                          \
            float u5 = __shfl_up_sync(M, r5, 1);                      \
            u5 = Lx ? u5 : 0.0f;                                      \
            const float n0 = qq.w * (r0 + u5);                        \
            const float n1 = qq.x * fmaf(a1, u5, r1 + r0);            \
            const float n2 = qq.w * (r2 + r1);                        \
            const float n3 = qq.y * fmaf(a3, r1, r3 + r2);            \
            const float n4 = qq.w * (r4 + r3);                        \
            const float n5 = qq.z * fmaf(a5, r3, r5 + r4);            \
            r0 = n0; r1 = n1; r2 = n2; r3 = n3; r4 = n4; r5 = n5; }

#pragma unroll
        for (int j = 1; j < 8; ++j) FSTEP(j, j - 1);
        E += renorm6(r0, r1, r2, r3, r4, r5);
        for (int tb = 8; tb < 128; tb += 8) {
#pragma unroll
            for (int j = 0; j < 8; ++j) FSTEP(tb + j, (j + 7) & 7);
            E += renorm6(r0, r1, r2, r3, r4, r5);
        }
#undef FSTEP

        const int s = 6 * Lx;
        exA[s]   = r0; exA[s+1] = r1; exA[s+2] = r2;
        exA[s+3] = r3; exA[s+4] = r4; exA[s+5] = r5;
        if (Lx == 0) exE[0] = E;
    }
    else if (wid == 1 && lane < 11) {
        // -------- backward: c_t = p_t * beta_t, t = 255..128 -------------
        int ilb = 2 * len;
        int ill = 2 * len - 1;
        if (ill < 0) ill += 65;

        const float b1 = (labs[3*Lx + 1] != labs[3*Lx]) ? 1.0f : 0.0f;
        const float b3 = (Lx < 10 && labs[3*Lx + 2] != labs[3*Lx + 1]) ? 1.0f : 0.0f;
        const float b5 = (Lx < 10 && labs[3*Lx + 3] != labs[3*Lx + 2]) ? 1.0f : 0.0f;

        float r0, r1, r2, r3, r4, r5;
        {
            const float4 q0 = rowp[GP_ * 255];
            const int s = 6 * Lx;
            r0 = (s     == ilb || s     == ill) ? q0.w : 0.0f;
            r1 = (s + 1 == ilb || s + 1 == ill) ? q0.x : 0.0f;
            r2 = (s + 2 == ilb || s + 2 == ill) ? q0.w : 0.0f;
            r3 = (s + 3 == ilb || s + 3 == ill) ? q0.y : 0.0f;
            r4 = (s + 4 == ilb || s + 4 == ill) ? q0.w : 0.0f;
            r5 = (s + 5 == ilb || s + 5 == ill) ? q0.z : 0.0f;
        }
        float4 q[8];
#pragma unroll
        for (int j = 0; j < 8; ++j) q[j] = rowp[GP_ * (254 - j)];
        int E = 0;

#define BSTEP(tt, idx) {                                              \
            const float4 qq = q[idx];                                 \
            q[idx] = rowp[GP_ * ((tt) - 8)];                          \
            float d0 = __shfl_down_sync(M, r0, 1);                    \
            float d1 = __shfl_down_sync(M, r1, 1);                    \
            d0 = (Lx < 10) ? d0 : 0.0f;                               \
            d1 = (Lx < 10) ? d1 : 0.0f;                               \
            const float n0 = qq.w * (r0 + r1);                        \
            const float n1 = qq.x * fmaf(b1, r3, r1 + r2);            \
            const float n2 = qq.w * (r2 + r3);                        \
            const float n3 = qq.y * fmaf(b3, r5, r3 + r4);            \
            const float n4 = qq.w * (r4 + r5);                        \
            const float n5 = qq.z * fmaf(b5, d1, r5 + d0);            \
            r0 = n0; r1 = n1; r2 = n2; r3 = n3; r4 = n4; r5 = n5; }

#pragma unroll
        for (int j = 0; j < 7; ++j) BSTEP(254 - j, j);
        E += renorm6(r0, r1, r2, r3, r4, r5);
        for (int tb = 247; tb >= 135; tb -= 8) {
#pragma unroll
            for (int j = 0; j < 8; ++j) BSTEP(tb - j, (j + 7) & 7);
            E += renorm6(r0, r1, r2, r3, r4, r5);
        }
#undef BSTEP

        // beta_127 combine (no p multiply) from c_128
        float d0 = __shfl_down_sync(M, r0, 1);
        float d1 = __shfl_down_sync(M, r1, 1);
        d0 = (Lx < 10) ? d0 : 0.0f;
        d1 = (Lx < 10) ? d1 : 0.0f;
        const int s = 6 * Lx;
        exB[s]   = r0 + r1;
        exB[s+1] = fmaf(b1, r3, r1 + r2);
        exB[s+2] = r2 + r3;
        exB[s+3] = fmaf(b3, r5, r3 + r4);
        exB[s+4] = r4 + r5;
        exB[s+5] = fmaf(b5, d1, r5 + d0);
        if (Lx == 0) exE[1] = E;
    }
    __syncthreads();

    // combine: P = sum over 66 slots of alpha_127 * beta_127
    if (wid == 0) {
        float part = exA[lane] * exB[lane] + exA[lane + 32] * exB[lane + 32];
        if (lane < 2) part += exA[lane + 64] * exB[lane + 64];
#pragma unroll
        for (int o = 16; o; o >>= 1)
            part += __shfl_xor_sync(FULLMASK, part, o);
        if (lane == 0) {
            const float LN2 = 0.6931471805599453f;
            out[b] = -(logf(part) +
                       (float)(exE[0] + exE[1] - PRE_E * T_) * LN2);
        }
    }
}

extern "C" void kernel_launch(void* const* d_in, const int* in_sizes, int n_in,
                              void* d_out, int out_size)
{
    (void)n_in; (void)out_size;
    const int*   y_true;
    const float* y_pred;
    if (in_sizes[0] == B_ * L_) {
        y_true = (const int*)d_in[0];
        y_pred = (const float*)d_in[1];
    } else {
        y_true = (const int*)d_in[1];
        y_pred = (const float*)d_in[0];
    }
    ctc_gather_kernel<<<B_ * 8, 256>>>(y_true, y_pred);
    ctc_scan_kernel<<<B_, 64>>>(y_true, (float*)d_out);
}

// round 17
// speedup vs baseline: 1.2066x; 1.0525x over previous
#include <cuda_runtime.h>

#define FULLMASK 0xffffffffu

constexpr int   B_     = 256;
constexpr int   T_     = 256;
constexpr int   C_     = 1024;
constexpr int   L_     = 32;
constexpr int   BLANK_ = C_ - 1;
constexpr int   GP_    = 11;      // float4 groups per row
constexpr int   RF_    = 44;      // floats per row
constexpr float PRE    = 512.0f;
constexpr int   PRE_E  = 9;
constexpr float EPS    = 1e-7f;
constexpr float EPS_S  = EPS * PRE;

// transposed compact scratch: row (b,t) = 11 float4 groups of
// [lab(3L), lab(3L+1), lab(3L+2), blank]; group10.z = 0 pad
__device__ float g_scr[(size_t)B_ * T_ * RF_];

__device__ __forceinline__ float ldg_cs(const float* p) {
    float v;
    asm volatile("ld.global.cs.f32 %0, [%1];" : "=f"(v) : "l"(p));
    return v;
}
__device__ __forceinline__ int renorm6(float& r0, float& r1, float& r2,
                                       float& r3, float& r4, float& r5) {
    float m = fmaxf(fmaxf(fmaxf(r0, r1), fmaxf(r2, r3)), fmaxf(r4, r5));
    int im = __float_as_int(m);
    asm volatile("redux.sync.max.s32 %0, %1, 0x7ff;" : "=r"(im) : "r"(im));
    const int e = (im >> 23) - 127;
    const float sc = __int_as_float((127 - e) << 23);  // exact 2^-e
    r0 *= sc; r1 *= sc; r2 *= sc; r3 *= sc; r4 *= sc; r5 *= sc;
    return e;
}

// ---------------------------------------------------------------------------
// Kernel 1: saturating gather (unchanged from R16; ~27 us with .cs reads)
// ---------------------------------------------------------------------------
__global__ __launch_bounds__(256)
void ctc_gather_kernel(const int* __restrict__ y_true,
                       const float* __restrict__ y_pred)
{
    __shared__ int labsx[33];   // [blank, lab0..lab31]

    const int bid   = blockIdx.x;
    const int b     = bid >> 3;
    const int chunk = (bid & 7) << 5;
    const int tid   = threadIdx.x;

    if (tid < 33)
        labsx[tid] = tid ? __ldg(y_true + b * L_ + tid - 1) : BLANK_;
    __syncthreads();

    const float* base = y_pred + ((size_t)b * T_ + chunk) * C_;

    float v[5];
    int   rr[5], ww[5];
#pragma unroll
    for (int i = 0; i < 5; ++i) {
        const int f = tid + i * 256;
        if (f < 1056) {
            const int row = f / 33;
            const int w   = f - 33 * row;
            rr[i] = row; ww[i] = w;
            const int cls = (w < 32) ? labsx[1 + w] : labsx[0];
            v[i] = ldg_cs(base + (size_t)row * C_ + cls);
        }
    }
#pragma unroll
    for (int i = 0; i < 5; ++i) {
        const int f = tid + i * 256;
        if (f < 1056) {
            float* orow = g_scr + ((size_t)b * T_ + chunk + rr[i]) * RF_;
            const float val = fmaf(v[i], PRE, EPS_S);
            if (ww[i] < 32) {
                const int g = ww[i] / 3;
                orow[g * 4 + (ww[i] - 3 * g)] = val;
            } else {
#pragma unroll
                for (int k = 0; k < 11; ++k) orow[4 * k + 3] = val;
                orow[42] = 0.0f;   // pad state
            }
        }
    }
}

// ---------------------------------------------------------------------------
// Kernel 2: per-batch scan from global scratch, 16-deep float4 prefetch ring
// (two 8-entry banks, compile-time indices) to cover DRAM latency.
// ---------------------------------------------------------------------------
__global__ __launch_bounds__(64)
void ctc_scan_kernel(const int* __restrict__ y_true,
                     float* __restrict__ out)
{
    __shared__ int   labs[L_];
    __shared__ float exA[66], exB[66];
    __shared__ int   exE[2];

    const int b    = blockIdx.x;
    const int tid  = threadIdx.x;
    const int lane = tid & 31;
    const int wid  = tid >> 5;
    const unsigned M = 0x7FFu;

    if (tid < L_) labs[tid] = __ldg(y_true + b * L_ + tid);
    __syncthreads();

    const unsigned nzm = __ballot_sync(FULLMASK, labs[lane] != 0);
    const int len = __popc(nzm);

    const int Lx = lane;
    const float4* rowp = ((const float4*)(g_scr + (size_t)b * T_ * RF_)) + Lx;

    if (wid == 0 && lane < 11) {
        // ---------------- forward: alpha_0 .. alpha_127 ----------------
        const float a1 = (Lx == 0 || labs[3*Lx] != labs[3*Lx - 1]) ? 1.0f : 0.0f;
        const float a3 = (labs[3*Lx + 1] != labs[3*Lx]) ? 1.0f : 0.0f;
        const float a5 = (Lx < 10 && labs[3*Lx + 2] != labs[3*Lx + 1]) ? 1.0f : 0.0f;

        float r0 = 0, r1 = 0, r2 = 0, r3 = 0, r4 = 0, r5 = 0;
        {
            const float4 q0 = rowp[0];
            if (Lx == 0) { r0 = q0.w; r1 = q0.x; }
        }
        float4 qA[8], qB[8];
#pragma unroll
        for (int j = 0; j < 8; ++j) qA[j] = rowp[GP_ * (1 + j)];
#pragma unroll
        for (int j = 0; j < 8; ++j) qB[j] = rowp[GP_ * (9 + j)];
        int E = 0;

#define FSTEP(QQ, tt, idx) {                                          \
            const float4 qq = QQ[idx];                                \
            QQ[idx] = rowp[GP_ * ((tt) + 16)];                        \
            float u5 = __shfl_up_sync(M, r5, 1);                      \
            u5 = Lx ? u5 : 0.0f;                                      \
            const float n0 = qq.w * (r0 + u5);                        \
            const float n1 = qq.x * fmaf(a1, u5, r1 + r0);            \
            const float n2 = qq.w * (r2 + r1);                        \
            const float n3 = qq.y * fmaf(a3, r1, r3 + r2);            \
            const float n4 = qq.w * (r4 + r3);                        \
            const float n5 = qq.z * fmaf(a5, r3, r5 + r4);            \
            r0 = n0; r1 = n1; r2 = n2; r3 = n3; r4 = n4; r5 = n5; }

        int t0 = 1;
        for (int bp = 0; bp < 7; ++bp) {        // t = 1 .. 112
#pragma unroll
            for (int j = 0; j < 8; ++j) FSTEP(qA, t0 + j, j);
            E += renorm6(r0, r1, r2, r3, r4, r5);
#pragma unroll
            for (int j = 0; j < 8; ++j) FSTEP(qB, t0 + 8 + j, j);
            E += renorm6(r0, r1, r2, r3, r4, r5);
            t0 += 16;
        }
#pragma unroll
        for (int j = 0; j < 8; ++j) FSTEP(qA, 113 + j, j);   // t = 113..120
        E += renorm6(r0, r1, r2, r3, r4, r5);
#pragma unroll
        for (int j = 0; j < 7; ++j) FSTEP(qB, 121 + j, j);   // t = 121..127
        E += renorm6(r0, r1, r2, r3, r4, r5);
#undef FSTEP

        const int s = 6 * Lx;
        exA[s]   = r0; exA[s+1] = r1; exA[s+2] = r2;
        exA[s+3] = r3; exA[s+4] = r4; exA[s+5] = r5;
        if (Lx == 0) exE[0] = E;
    }
    else if (wid == 1 && lane < 11) {
        // -------- backward: c_t = p_t * beta_t, t = 255..128 -------------
        int ilb = 2 * len;
        int ill = 2 * len - 1;
        if (ill < 0) ill += 65;

        const float b1 = (labs[3*Lx + 1] != labs[3*Lx]) ? 1.0f : 0.0f;
        const float b3 = (Lx < 10 && labs[3*Lx + 2] != labs[3*Lx + 1]) ? 1.0f : 0.0f;
        const float b5 = (Lx < 10 && labs[3*Lx + 3] != labs[3*Lx + 2]) ? 1.0f : 0.0f;

        float r0, r1, r2, r3, r4, r5;
        {
            const float4 q0 = rowp[GP_ * 255];
            const int s = 6 * Lx;
            r0 = (s     == ilb || s     == ill) ? q0.w : 0.0f;
            r1 = (s + 1 == ilb || s + 1 == ill) ? q0.x : 0.0f;
            r2 = (s + 2 == ilb || s + 2 == ill) ? q0.w : 0.0f;
            r3 = (s + 3 == ilb || s + 3 == ill) ? q0.y : 0.0f;
            r4 = (s + 4 == ilb || s + 4 == ill) ? q0.w : 0.0f;
            r5 = (s + 5 == ilb || s + 5 == ill) ? q0.z : 0.0f;
        }
        float4 qA[8], qB[8];
#pragma unroll
        for (int j = 0; j < 8; ++j) qA[j] = rowp[GP_ * (254 - j)];
#pragma unroll
        for (int j = 0; j < 8; ++j) qB[j] = rowp[GP_ * (246 - j)];
        int E = 0;

#define BSTEP(QQ, tt, idx) {                                          \
            const float4 qq = QQ[idx];                                \
            QQ[idx] = rowp[GP_ * ((tt) - 16)];                        \
            float d0 = __shfl_down_sync(M, r0, 1);                    \
            float d1 = __shfl_down_sync(M, r1, 1);                    \
            d0 = (Lx < 10) ? d0 : 0.0f;                               \
            d1 = (Lx < 10) ? d1 : 0.0f;                               \
            const float n0 = qq.w * (r0 + r1);                        \
            const float n1 = qq.x * fmaf(b1, r3, r1 + r2);            \
            const float n2 = qq.w * (r2 + r3);                        \
            const float n3 = qq.y * fmaf(b3, r5, r3 + r4);            \
            const float n4 = qq.w * (r4 + r5);                        \
            const float n5 = qq.z * fmaf(b5, d1, r5 + d0);            \
            r0 = n0; r1 = n1; r2 = n2; r3 = n3; r4 = n4; r5 = n5; }

        int t0 = 254;
        for (int bp = 0; bp < 7; ++bp) {        // t = 254 .. 143
#pragma unroll
            for (int j = 0; j < 8; ++j) BSTEP(qA, t0 - j, j);
            E += renorm6(r0, r1, r2, r3, r4, r5);
#pragma unroll
            for (int j = 0; j < 8; ++j) BSTEP(qB, t0 - 8 - j, j);
            E += renorm6(r0, r1, r2, r3, r4, r5);
            t0 -= 16;
        }
#pragma unroll
        for (int j = 0; j < 8; ++j) BSTEP(qA, 142 - j, j);   // t = 142..135
        E += renorm6(r0, r1, r2, r3, r4, r5);
#pragma unroll
        for (int j = 0; j < 7; ++j) BSTEP(qB, 134 - j, j);   // t = 134..128
        E += renorm6(r0, r1, r2, r3, r4, r5);
#undef BSTEP

        // beta_127 combine (no p multiply) from c_128
        float d0 = __shfl_down_sync(M, r0, 1);
        float d1 = __shfl_down_sync(M, r1, 1);
        d0 = (Lx < 10) ? d0 : 0.0f;
        d1 = (Lx < 10) ? d1 : 0.0f;
        const int s = 6 * Lx;
        exB[s]   = r0 + r1;
        exB[s+1] = fmaf(b1, r3, r1 + r2);
        exB[s+2] = r2 + r3;
        exB[s+3] = fmaf(b3, r5, r3 + r4);
        exB[s+4] = r4 + r5;
        exB[s+5] = fmaf(b5, d1, r5 + d0);
        if (Lx == 0) exE[1] = E;
    }
    __syncthreads();

    // combine: P = sum over 66 slots of alpha_127 * beta_127
    if (wid == 0) {
        float part = exA[lane] * exB[lane] + exA[lane + 32] * exB[lane + 32];
        if (lane < 2) part += exA[lane + 64] * exB[lane + 64];
#pragma unroll
        for (int o = 16; o; o >>= 1)
            part += __shfl_xor_sync(FULLMASK, part, o);
        if (lane == 0) {
            const float LN2 = 0.6931471805599453f;
            out[b] = -(logf(part) +
                       (float)(exE[0] + exE[1] - PRE_E * T_) * LN2);
        }
    }
}

extern "C" void kernel_launch(void* const* d_in, const int* in_sizes, int n_in,
                              void* d_out, int out_size)
{
    (void)n_in; (void)out_size;
    const int*   y_true;
    const float* y_pred;
    if (in_sizes[0] == B_ * L_) {
        y_true = (const int*)d_in[0];
        y_pred = (const float*)d_in[1];
    } else {
        y_true = (const int*)d_in[1];
        y_pred = (const float*)d_in[0];
    }
    ctc_gather_kernel<<<B_ * 8, 256>>>(y_true, y_pred);
    ctc_scan_kernel<<<B_, 64>>>(y_true, (float*)d_out);
}